// round 12
// baseline (speedup 1.0000x reference)
#include <cuda_runtime.h>
#include <cuda_bf16.h>
#include <mma.h>
#include <math.h>

#define NN 1024
#define H 256

typedef unsigned long long u64;
typedef unsigned int u32;

using namespace nvcuda;

// ---------------- f32x2 packed helpers (sm_103a) ----------------------------
__device__ __forceinline__ u64 add2(u64 a, u64 b) {
    u64 r; asm("add.rn.f32x2 %0,%1,%2;" : "=l"(r) : "l"(a), "l"(b)); return r;
}
__device__ __forceinline__ void fma2(u64& d, u64 a, u64 b) {
    asm("fma.rn.f32x2 %0,%1,%2,%0;" : "+l"(d) : "l"(a), "l"(b));
}
__device__ __forceinline__ float2 unpack2(u64 v) {
    float2 r; asm("mov.b64 {%0,%1},%2;" : "=f"(r.x), "=f"(r.y) : "l"(v)); return r;
}

// ---------------- cp.async helpers ------------------------------------------
__device__ __forceinline__ void cp8(void* dst_smem, const void* src) {
    unsigned d = (unsigned)__cvta_generic_to_shared(dst_smem);
    asm volatile("cp.async.ca.shared.global [%0], [%1], 8;" :: "r"(d), "l"(src));
}
__device__ __forceinline__ void cp16s(unsigned dst_smem, const void* src) {
    asm volatile("cp.async.cg.shared.global [%0], [%1], 16;" :: "r"(dst_smem), "l"(src));
}
__device__ __forceinline__ void cp_commit() {
    asm volatile("cp.async.commit_group;" ::: "memory");
}
template <int N>
__device__ __forceinline__ void cp_wait() {
    asm volatile("cp.async.wait_group %0;" :: "n"(N) : "memory");
}
__device__ __forceinline__ u32 s2u(const void* p) {
    u32 a; asm("{ .reg .u64 t; cvta.to.shared.u64 t, %1; cvt.u32.u64 %0, t; }"
               : "=r"(a) : "l"(p));
    return a;
}

__device__ __forceinline__ unsigned short bfbits(float x) {
    __nv_bfloat16 h = __float2bfloat16(x);
    return *reinterpret_cast<unsigned short*>(&h);
}
__device__ __forceinline__ float bffloat(unsigned short u) {
    __nv_bfloat16 h;
    *reinterpret_cast<unsigned short*>(&h) = u;
    return __bfloat162float(h);
}

// ---------------- scratch ----------------------------------------------------
__device__ float g_P[8 * NN * H];
__device__ float g_Q[4 * NN * H];
__device__ float g_X1[NN * H];
__device__ float g_X2[NN * H];
__device__ float g_hij[2 * NN * H];
__device__ float g_diP[NN * H];
__device__ float g_E[NN * NN];
__device__ float g_S[256 * 512];
__device__ float g_sc1[H], g_sh1[H];
__device__ float g_sc2[H], g_sh2[H];
__device__ float g_ci[NN], g_dj[NN];
__device__ int g_pos[NN], g_perm[NN], g_lsort[NN], g_cls[17];
__device__ int g_tlist[1024];
__device__ int g_tcnt[1];
__device__ __align__(16) __nv_bfloat16 g_Abf[NN * 6144];   // GEMM1 A'; reused for act splits
__device__ __align__(16) __nv_bfloat16 g_Bbf[256 * 6144];  // GEMM1 B'; reused for W splits

// ---------------- conv: features -> split-bf16 A' (K'=6144) -----------------
__global__ void conv_feats(const float* __restrict__ F, __nv_bfloat16* __restrict__ Ap) {
    const int gid = blockIdx.x * 256 + threadIdx.x;
    const int row = gid >> 9;
    const int kq = (gid & 511) * 4;
    float4 v = *(const float4*)&F[(size_t)row * 2048 + kq];
    float a[4] = {v.x, v.y, v.z, v.w};
    unsigned short hb[4], lb[4];
#pragma unroll
    for (int j = 0; j < 4; j++) {
        hb[j] = bfbits(a[j]);
        lb[j] = bfbits(a[j] - bffloat(hb[j]));
    }
    uint4 u;
    u.x = hb[0] | ((u32)lb[0] << 16);
    u.y = hb[1] | ((u32)lb[1] << 16);
    u.z = hb[2] | ((u32)lb[2] << 16);
    u.w = hb[3] | ((u32)lb[3] << 16);
    *(uint4*)&Ap[(size_t)row * 6144 + 2 * kq] = u;
    uint2 w;
    w.x = hb[0] | ((u32)hb[1] << 16);
    w.y = hb[2] | ((u32)hb[3] << 16);
    *(uint2*)&Ap[(size_t)row * 6144 + 4096 + kq] = w;
}

// ---------------- conv: W1 -> split-bf16 B' (transposed, K'=6144) -----------
__global__ void conv_W1(const float* __restrict__ W, __nv_bfloat16* __restrict__ Bp) {
    __shared__ float sW[64][65];
    const int kb = blockIdx.x, nb = blockIdx.y;
    const int t = threadIdx.x;
#pragma unroll
    for (int e = 0; e < 16; e++) {
        int id = t + e * 256;
        int kr = id >> 6, nc = id & 63;
        sW[kr][nc] = W[(size_t)(kb * 64 + kr) * 256 + nb * 64 + nc];
    }
    __syncthreads();
#pragma unroll
    for (int e = 0; e < 16; e++) {
        int id = t + e * 256;
        int nr = id >> 6, kc = id & 63;
        float x = sW[kc][nr];
        unsigned short hb = bfbits(x);
        unsigned short lb = bfbits(x - bffloat(hb));
        int ng = nb * 64 + nr, kg = kb * 64 + kc;
        ((u32*)Bp)[(size_t)ng * 3072 + kg] = hb | ((u32)hb << 16);
        *reinterpret_cast<unsigned short*>(&Bp[(size_t)ng * 6144 + 4096 + kg]) = lb;
    }
}

// ---------------- conv: act = relu(BN(X)) -> split-bf16 [1024][768] ----------
__global__ void conv_act(const float* __restrict__ X, const float* __restrict__ sc,
                         const float* __restrict__ sh, __nv_bfloat16* __restrict__ Ap) {
    const int gid = blockIdx.x * 256 + threadIdx.x;  // 65536
    const int row = gid >> 6;
    const int c4 = gid & 63;
    const int kq = c4 * 4;
    float4 v = ((const float4*)X)[(size_t)row * 64 + c4];
    float4 s = ((const float4*)sc)[c4];
    float4 h = ((const float4*)sh)[c4];
    float a[4];
    a[0] = fmaxf(fmaf(v.x, s.x, h.x), 0.f);
    a[1] = fmaxf(fmaf(v.y, s.y, h.y), 0.f);
    a[2] = fmaxf(fmaf(v.z, s.z, h.z), 0.f);
    a[3] = fmaxf(fmaf(v.w, s.w, h.w), 0.f);
    unsigned short hb[4], lb[4];
#pragma unroll
    for (int j = 0; j < 4; j++) {
        hb[j] = bfbits(a[j]);
        lb[j] = bfbits(a[j] - bffloat(hb[j]));
    }
    uint4 u;
    u.x = hb[0] | ((u32)lb[0] << 16);
    u.y = hb[1] | ((u32)lb[1] << 16);
    u.z = hb[2] | ((u32)lb[2] << 16);
    u.w = hb[3] | ((u32)lb[3] << 16);
    *(uint4*)&Ap[(size_t)row * 768 + 2 * kq] = u;
    uint2 w;
    w.x = hb[0] | ((u32)hb[1] << 16);
    w.y = hb[2] | ((u32)hb[3] << 16);
    *(uint2*)&Ap[(size_t)row * 768 + 512 + kq] = w;
}

// ---------------- conv: W[K=256,N=256] -> split-bf16 B [n][768] (z halves) ---
__global__ void conv_wT(const float* __restrict__ W, __nv_bfloat16* __restrict__ Bp) {
    __shared__ float sW[64][65];
    const int kb = blockIdx.x, nb = blockIdx.y, z = blockIdx.z;
    const int t = threadIdx.x;
    const float* Ws = W + (size_t)z * 256 * 256;
    __nv_bfloat16* Bd = Bp + (size_t)z * 256 * 768;
#pragma unroll
    for (int e = 0; e < 16; e++) {
        int id = t + e * 256;
        int kr = id >> 6, nc = id & 63;
        sW[kr][nc] = Ws[(size_t)(kb * 64 + kr) * 256 + nb * 64 + nc];
    }
    __syncthreads();
#pragma unroll
    for (int e = 0; e < 16; e++) {
        int id = t + e * 256;
        int nr = id >> 6, kc = id & 63;
        float x = sW[kc][nr];
        unsigned short hb = bfbits(x);
        unsigned short lb = bfbits(x - bffloat(hb));
        int ng = nb * 64 + nr, kg = kb * 64 + kc;
        ((u32*)Bd)[(size_t)ng * 384 + kg] = hb | ((u32)hb << 16);
        *reinterpret_cast<unsigned short*>(&Bd[(size_t)ng * 768 + 512 + kg]) = lb;
    }
}

// ---------------- generic wmma GEMM: C[1024,256] = A @ B^T -------------------
// Block tile 128x64, 256 thr, warp tile 32x32. K chunk = 64, double-buffered.
// DUAL: z>>1 selects B plane (B + (z>>1)*256*ld), z&1 selects K chunk group.
// else: z selects K chunk group. Output plane z.
template <bool DUAL>
__global__ __launch_bounds__(256) void wmma_bf16(
    const __nv_bfloat16* __restrict__ A, const __nv_bfloat16* __restrict__ B,
    float* __restrict__ C0, int ld, int kchunksPerZ) {
    extern __shared__ char dsm[];
    char* base = (char*)(((size_t)dsm + 1023) & ~(size_t)1023);
    __nv_bfloat16* smA[2] = {(__nv_bfloat16*)base,
                             (__nv_bfloat16*)(base + 18432)};
    __nv_bfloat16* smB[2] = {(__nv_bfloat16*)(base + 36864),
                             (__nv_bfloat16*)(base + 46080)};
    const u32 uA[2] = {s2u(smA[0]), s2u(smA[1])};
    const u32 uB[2] = {s2u(smB[0]), s2u(smB[1])};

    const int t = threadIdx.x;
    const int wid = t >> 5;
    const int wm = wid >> 1;
    const int wn = wid & 1;
    const int J = blockIdx.x * 64;
    const int I = blockIdx.y * 128;
    const int z = blockIdx.z;
    const int kbase = (DUAL ? (z & 1) : z) * kchunksPerZ * 64;
    const __nv_bfloat16* Bp = DUAL ? (B + (size_t)(z >> 1) * 256 * ld) : B;

    auto stage = [&](int chunk, int buf) {
        const int k0 = kbase + chunk * 64;
#pragma unroll
        for (int e = 0; e < 4; e++) {
            int id = t + e * 256;
            int r = id >> 3, c = id & 7;
            cp16s(uA[buf] + r * 144 + c * 16,
                  A + (size_t)(I + r) * ld + k0 + c * 8);
        }
#pragma unroll
        for (int e = 0; e < 2; e++) {
            int id = t + e * 256;
            int r = id >> 3, c = id & 7;
            cp16s(uB[buf] + r * 144 + c * 16,
                  Bp + (size_t)(J + r) * ld + k0 + c * 8);
        }
    };

    wmma::fragment<wmma::accumulator, 16, 16, 16, float> acc[2][2];
#pragma unroll
    for (int i = 0; i < 2; i++)
#pragma unroll
        for (int j = 0; j < 2; j++) wmma::fill_fragment(acc[i][j], 0.0f);

    stage(0, 0);
    cp_commit();

    for (int c = 0; c < kchunksPerZ; c++) {
        const int buf = c & 1;
        if (c + 1 < kchunksPerZ) {
            stage(c + 1, buf ^ 1);
            cp_commit();
            cp_wait<1>();
        } else {
            cp_wait<0>();
        }
        __syncthreads();
#pragma unroll
        for (int k16 = 0; k16 < 4; k16++) {
            wmma::fragment<wmma::matrix_a, 16, 16, 16, __nv_bfloat16,
                           wmma::row_major> af[2];
            wmma::fragment<wmma::matrix_b, 16, 16, 16, __nv_bfloat16,
                           wmma::col_major> bf[2];
#pragma unroll
            for (int i = 0; i < 2; i++)
                wmma::load_matrix_sync(
                    af[i], smA[buf] + (wm * 32 + i * 16) * 72 + k16 * 16, 72);
#pragma unroll
            for (int j = 0; j < 2; j++)
                wmma::load_matrix_sync(
                    bf[j], smB[buf] + (wn * 32 + j * 16) * 72 + k16 * 16, 72);
#pragma unroll
            for (int i = 0; i < 2; i++)
#pragma unroll
                for (int j = 0; j < 2; j++)
                    wmma::mma_sync(acc[i][j], af[i], bf[j], acc[i][j]);
        }
        __syncthreads();
    }

    float* Cp = C0 + (size_t)z * NN * H;
#pragma unroll
    for (int i = 0; i < 2; i++)
#pragma unroll
        for (int j = 0; j < 2; j++)
            wmma::store_matrix_sync(
                Cp + (size_t)(I + wm * 32 + i * 16) * H + J + wn * 32 + j * 16,
                acc[i][j], H, wmma::mem_row_major);
}

// ---------------- GEMM4: E(perm, block-diag) @ diP, dynamic k-range ---------
__global__ __launch_bounds__(128) void gemm4_range(
    const float* __restrict__ E, const float* __restrict__ diP,
    const int* __restrict__ lsort, const int* __restrict__ cls,
    float* __restrict__ C) {
    __shared__ float As[2][32][20];
    __shared__ float Bs[2][64][20];

    const int t = threadIdx.x;
    const int tx = t & 15;
    const int ty = t >> 4;
    const int I = blockIdx.y * 32;
    const int J = blockIdx.x * 64;

    const int lmin = lsort[I];
    const int lmax = lsort[I + 31];
    const int kmin = cls[lmin] & ~15;
    int kmax = (cls[lmax + 1] + 15) & ~15;
    if (kmax > NN) kmax = NN;
    const int kiters = (kmax - kmin) >> 4;

    float4 fa;
    float fb[8];
    const int ar = t >> 2, ac4 = t & 3;
    const int bc = t & 63, bkh = (t >> 6) * 8;

    auto loadA = [&](int kt) {
        const int kc = kmin + kt * 16 + ac4 * 4;
        fa = *(const float4*)&E[(size_t)(I + ar) * NN + kc];
    };
    auto loadB = [&](int kt) {
        const int k0 = kmin + kt * 16 + bkh;
#pragma unroll
        for (int e = 0; e < 8; e++)
            fb[e] = diP[(size_t)(k0 + e) * H + J + bc];
    };
    auto stageS = [&](int buf) {
        *(float4*)&As[buf][ar][ac4 * 4] = fa;
        *(float4*)&Bs[buf][bc][bkh] = make_float4(fb[0], fb[1], fb[2], fb[3]);
        *(float4*)&Bs[buf][bc][bkh + 4] = make_float4(fb[4], fb[5], fb[6], fb[7]);
    };

    u64 acc[4][4];
#pragma unroll
    for (int m = 0; m < 4; m++)
#pragma unroll
        for (int n = 0; n < 4; n++) acc[m][n] = 0ull;

    loadA(0); loadB(0);
    stageS(0);
    __syncthreads();

    for (int kt = 0; kt < kiters; kt++) {
        const int buf = kt & 1;
        if (kt + 1 < kiters) { loadA(kt + 1); loadB(kt + 1); }
#pragma unroll
        for (int g = 0; g < 4; g++) {
            float4 av[4], bv[4];
#pragma unroll
            for (int m = 0; m < 4; m++)
                av[m] = *(const float4*)&As[buf][ty * 4 + m][g * 4];
#pragma unroll
            for (int n = 0; n < 4; n++)
                bv[n] = *(const float4*)&Bs[buf][tx + n * 16][g * 4];
#pragma unroll
            for (int m = 0; m < 4; m++) {
                const u64 a01 = *(const u64*)&av[m].x;
                const u64 a23 = *(const u64*)&av[m].z;
#pragma unroll
                for (int n = 0; n < 4; n++) {
                    fma2(acc[m][n], a01, *(const u64*)&bv[n].x);
                    fma2(acc[m][n], a23, *(const u64*)&bv[n].z);
                }
            }
        }
        if (kt + 1 < kiters) {
            stageS(buf ^ 1);
            __syncthreads();
        }
    }

#pragma unroll
    for (int m = 0; m < 4; m++) {
        const int row = I + ty * 4 + m;
#pragma unroll
        for (int n = 0; n < 4; n++) {
            const int col = J + tx + n * 16;
            float2 p = unpack2(acc[m][n]);
            C[(size_t)row * H + col] = p.x + p.y;
        }
    }
}

// ---------------- BN stats phase1 / phase2 -----------------------------------
template <int NP>
__global__ void stats_phase1(const float* __restrict__ P, const float* __restrict__ bias,
                             float* __restrict__ X, float* __restrict__ S) {
    const int t = threadIdx.x;
    const int c4 = t & 63;
    const int rg = t >> 6;
    const int row = blockIdx.x * 4 + rg;
    float4 bv = ((const float4*)bias)[c4];
    constexpr size_t Q = NN * H / 4;
    size_t idx = (size_t)row * 64 + c4;
    float4 v = bv;
#pragma unroll
    for (int p = 0; p < NP; p++) {
        float4 a = ((const float4*)P)[(size_t)p * Q + idx];
        v.x += a.x; v.y += a.y; v.z += a.z; v.w += a.w;
    }
    ((float4*)X)[idx] = v;
    float4 q;
    q.x = v.x * v.x; q.y = v.y * v.y; q.z = v.z * v.z; q.w = v.w * v.w;
    __shared__ float4 sm[4][64], qm[4][64];
    sm[rg][c4] = v;
    qm[rg][c4] = q;
    __syncthreads();
    if (t < 64) {
        float4 S4 = make_float4(0.f, 0.f, 0.f, 0.f);
        float4 Q4 = make_float4(0.f, 0.f, 0.f, 0.f);
#pragma unroll
        for (int p = 0; p < 4; p++) {
            float4 a = sm[p][t], b = qm[p][t];
            S4.x += a.x; S4.y += a.y; S4.z += a.z; S4.w += a.w;
            Q4.x += b.x; Q4.y += b.y; Q4.z += b.z; Q4.w += b.w;
        }
        ((float4*)S)[blockIdx.x * 128 + t] = S4;
        ((float4*)S)[blockIdx.x * 128 + 64 + t] = Q4;
    }
}

__global__ void stats_phase2(const float* __restrict__ S, const float* __restrict__ g,
                             const float* __restrict__ bt, float* __restrict__ sc,
                             float* __restrict__ sh) {
    const int t = threadIdx.x;
    const int c = blockIdx.x * 32 + (t & 31);
    const int pg = t >> 5;
    float s = 0.f, q = 0.f;
#pragma unroll
    for (int p = pg; p < 256; p += 8) {
        s += S[p * 512 + c];
        q += S[p * 512 + 256 + c];
    }
    __shared__ float sm[8][32], qm[8][32];
    sm[pg][t & 31] = s;
    qm[pg][t & 31] = q;
    __syncthreads();
    if (t < 32) {
        float S_ = 0.f, Q_ = 0.f;
#pragma unroll
        for (int p = 0; p < 8; p++) { S_ += sm[p][t]; Q_ += qm[p][t]; }
        const int col = blockIdx.x * 32 + t;
        float m = S_ * (1.f / NN);
        float var = Q_ * (1.f / NN) - m * m;
        float scv = g[col] * rsqrtf(var + 1e-5f);
        sc[col] = scv;
        sh[col] = bt[col] - m * scv;
    }
}

// ---------------- rank/sort kernel -------------------------------------------
__global__ void rank_kernel(const int* __restrict__ labels, int* __restrict__ pos,
                            int* __restrict__ perm, int* __restrict__ lsort,
                            int* __restrict__ cls, int* __restrict__ tcnt) {
    __shared__ int sl[NN];
    const int t = threadIdx.x;
    const int node = blockIdx.x * 128 + t;
#pragma unroll
    for (int e = 0; e < NN / 128; e++) sl[t + e * 128] = labels[t + e * 128];
    __syncthreads();
    const int my = sl[node];
    int r = 0;
#pragma unroll 8
    for (int j = 0; j < NN; j++) {
        int l = sl[j];
        r += (l < my) || (l == my && j < node);
    }
    pos[node] = r;
    perm[r] = node;
    lsort[r] = my;
    if (blockIdx.x == 0) {
        if (t <= 16) {
            int c = 0;
#pragma unroll 8
            for (int j = 0; j < NN; j++) c += (sl[j] < t);
            cls[t] = c;
        }
        if (t == 17) tcnt[0] = 0;
    }
}

// ---------------- diP[pos[r]] = relu(BN2(X2[r])) -----------------------------
__global__ void apply_relu_perm(const float* __restrict__ X, const float* __restrict__ sc,
                                const float* __restrict__ sh, const int* __restrict__ pos,
                                float* __restrict__ Y) {
    const int idx = blockIdx.x * 256 + threadIdx.x;
    const int row = idx >> 6;
    const int c4 = idx & 63;
    float4 v = ((const float4*)X)[idx];
    float4 s = ((const float4*)sc)[c4];
    float4 h = ((const float4*)sh)[c4];
    float4 y;
    y.x = fmaxf(fmaf(v.x, s.x, h.x), 0.f);
    y.y = fmaxf(fmaf(v.y, s.y, h.y), 0.f);
    y.z = fmaxf(fmaf(v.z, s.z, h.z), 0.f);
    y.w = fmaxf(fmaf(v.w, s.w, h.w), 0.f);
    ((float4*)Y)[(size_t)pos[row] * 64 + c4] = y;
}

// ---------------- combine GEMM3 partials + ci/dj (permuted writes) -----------
__global__ void combine_cidj(const float* __restrict__ Q, const float* __restrict__ bwe1,
                             const float* __restrict__ We2, const int* __restrict__ pos,
                             float* __restrict__ hi, float* __restrict__ hjb,
                             float* __restrict__ ci, float* __restrict__ dj) {
    const int r = blockIdx.x;
    const int pr = pos[r];
    const int t = threadIdx.x;
    const bool isB = t >= 128;
    const int tt = t & 127;
    constexpr size_t PL = (size_t)NN * H;
    const float* P0 = Q + (isB ? 2 * PL : 0);
    const float* P1 = P0 + PL;
    float* dst = isB ? hjb : hi;
    float partial = 0.f;
#pragma unroll
    for (int e = 0; e < 2; e++) {
        const int c = tt + e * 128;
        float v = P0[(size_t)r * H + c] + P1[(size_t)r * H + c];
        if (isB) v += bwe1[c];
        dst[(size_t)pr * H + c] = v;
        partial = fmaf(v, We2[c], partial);
    }
#pragma unroll
    for (int o = 16; o > 0; o >>= 1) partial += __shfl_xor_sync(~0u, partial, o);
    __shared__ float red[8];
    if ((t & 31) == 0) red[t >> 5] = partial;
    __syncthreads();
    if (t == 0) ci[pr] = 0.5f * (red[0] + red[1] + red[2] + red[3]);
    if (t == 128) dj[pr] = 0.5f * (red[4] + red[5] + red[6] + red[7]);
}

// ---------------- zero E ------------------------------------------------------
__global__ void zero_E(float* __restrict__ E) {
    const int idx = blockIdx.x * 256 + threadIdx.x;
    ((float4*)E)[idx] = make_float4(0.f, 0.f, 0.f, 0.f);
}

// ---------------- worklist of active 32x32 tiles -----------------------------
__global__ void build_worklist(const int* __restrict__ lsort, int* __restrict__ tlist,
                               int* __restrict__ tcnt) {
    const int t = threadIdx.x;
    const int ti = t >> 5, tj = t & 31;
    const int I = ti * 32, J = tj * 32;
    bool act = (lsort[I] <= lsort[J + 31]) && (lsort[J] <= lsort[I + 31]);
    if (act) {
        int k = atomicAdd(tcnt, 1);
        tlist[k] = (ti << 16) | tj;
    }
}

// ---------------- sparse edge kernel -----------------------------------------
__global__ __launch_bounds__(128) void edge_sparse(
    const float* __restrict__ hi, const float* __restrict__ hjb,
    const float* __restrict__ We2, const float* __restrict__ bwe2,
    const int* __restrict__ lsort,
    const float* __restrict__ ci, const float* __restrict__ dj,
    const int* __restrict__ tlist, const int* __restrict__ tcnt,
    float* __restrict__ E) {
    __shared__ float2 sa[2][32][16];
    __shared__ float2 sb[2][32][16];
    __shared__ float sw[256];

    const int t = threadIdx.x;
    const int tx = t & 15;
    const int ty = t >> 4;
    sw[t] = 0.5f * We2[t];
    sw[t + 128] = 0.5f * We2[t + 128];
    const int n = tcnt[0];
    const float bw = bwe2[0];

    for (int w = blockIdx.x; w < n; w += gridDim.x) {
        const int tile = tlist[w];
        const int I = (tile >> 16) * 32;
        const int J = (tile & 0xffff) * 32;

        auto stage = [&](int c) {
            const int buf = c & 1;
            const int hoff = c * 32;
#pragma unroll
            for (int k = 0; k < 8; k++) {
                int p = t + k * 128;
                if (p < 512) {
                    int r = p >> 4, c2 = p & 15;
                    cp8(&sa[buf][r][c2 ^ (r & 15)],
                        hi + (size_t)(I + r) * H + hoff + c2 * 2);
                } else {
                    int q = p - 512;
                    int r = q >> 4, c2 = q & 15;
                    cp8(&sb[buf][r][c2 ^ (r & 15)],
                        hjb + (size_t)(J + r) * H + hoff + c2 * 2);
                }
            }
        };

        u64 acc[4][2];
#pragma unroll
        for (int m = 0; m < 4; m++)
#pragma unroll
            for (int nn2 = 0; nn2 < 2; nn2++) acc[m][nn2] = 0ull;

        stage(0);
        cp_commit();

        for (int c = 0; c < 8; c++) {
            if (c < 7) {
                stage(c + 1);
                cp_commit();
                cp_wait<1>();
            } else {
                cp_wait<0>();
            }
            __syncthreads();
            const int buf = c & 1;
            const float* swc = &sw[c * 32];
#pragma unroll
            for (int hp = 0; hp < 16; hp++) {
                u64 wv = *(const u64*)&swc[hp * 2];
                u64 aP[4], bP[2];
#pragma unroll
                for (int m = 0; m < 4; m++) {
                    const int r = ty + m * 8;
                    aP[m] = *(const u64*)&sa[buf][r][hp ^ (r & 15)];
                }
#pragma unroll
                for (int nn2 = 0; nn2 < 2; nn2++) {
                    const int r = tx + nn2 * 16;
                    bP[nn2] = *(const u64*)&sb[buf][r][hp ^ (r & 15)];
                }
#pragma unroll
                for (int m = 0; m < 4; m++)
#pragma unroll
                    for (int nn2 = 0; nn2 < 2; nn2++) {
                        u64 s = add2(aP[m], bP[nn2]) & 0x7FFFFFFF7FFFFFFFull;
                        fma2(acc[m][nn2], s, wv);
                    }
            }
            __syncthreads();
        }

#pragma unroll
        for (int m = 0; m < 4; m++) {
            const int i = I + ty + m * 8;
            const int la = lsort[i];
            const float cv = ci[i] + bw;
#pragma unroll
            for (int nn2 = 0; nn2 < 2; nn2++) {
                const int j = J + tx + nn2 * 16;
                float2 p = unpack2(acc[m][nn2]);
                float logit = p.x + p.y + cv + dj[j];
                float e = (la == lsort[j] && i != j)
                              ? 1.f / (1.f + __expf(-logit)) : 0.f;
                E[(size_t)i * NN + j] = e;
            }
        }
    }
}

// ---------------- final: wsum inline; out[perm[p]] = diP[p] + R[p]/wsum -----
__global__ void reduce_final(const float* __restrict__ P, const float* __restrict__ E,
                             const float* __restrict__ diP, const int* __restrict__ perm,
                             float* __restrict__ out) {
    const int t = threadIdx.x;
    const int rg = t >> 6;
    const int c4 = t & 63;
    const int p = blockIdx.x * 4 + rg;

    float s = 0.f;
    const float4* Er = (const float4*)(E + (size_t)p * NN);
#pragma unroll
    for (int e = 0; e < 4; e++) {
        float4 v = Er[c4 + e * 64];
        s += v.x + v.y + v.z + v.w;
    }
#pragma unroll
    for (int o = 16; o > 0; o >>= 1) s += __shfl_xor_sync(~0u, s, o);
    __shared__ float sm[8];
    if ((t & 31) == 0) sm[t >> 5] = s;
    __syncthreads();
    const float w = sm[rg * 2] + sm[rg * 2 + 1];
    const float inv = w > 0.f ? 1.f / w : 0.f;

    const size_t idx = (size_t)p * 64 + c4;
    float4 a = ((const float4*)P)[idx];
    float4 d = ((const float4*)diP)[idx];
    float4 o;
    o.x = fmaf(a.x, inv, d.x);
    o.y = fmaf(a.y, inv, d.y);
    o.z = fmaf(a.z, inv, d.z);
    o.w = fmaf(a.w, inv, d.w);
    ((float4*)out)[(size_t)perm[p] * 64 + c4] = o;
}

// ---------------- launch -----------------------------------------------------
extern "C" void kernel_launch(void* const* d_in, const int* in_sizes, int n_in,
                              void* d_out, int out_size) {
    const float* features = (const float*)d_in[0];
    const int* labels = (const int*)d_in[1];
    const float* W1 = (const float*)d_in[2];
    const float* b1 = (const float*)d_in[3];
    const float* g1 = (const float*)d_in[4];
    const float* bt1 = (const float*)d_in[5];
    const float* W2 = (const float*)d_in[6];
    const float* b2 = (const float*)d_in[7];
    const float* g2 = (const float*)d_in[8];
    const float* bt2 = (const float*)d_in[9];
    const float* We1 = (const float*)d_in[10];
    const float* bwe1 = (const float*)d_in[11];
    const float* We2 = (const float*)d_in[12];
    const float* bwe2 = (const float*)d_in[13];
    float* out = (float*)d_out;

    void *pP, *pQ, *pX1, *pX2, *phij, *pdiP, *pE, *pS;
    void *psc1, *psh1, *psc2, *psh2, *pci, *pdj;
    void *ppos, *pperm, *plsort, *pcls, *ptlist, *ptcnt, *pAbf, *pBbf;
    cudaGetSymbolAddress(&pP, g_P);
    cudaGetSymbolAddress(&pQ, g_Q);
    cudaGetSymbolAddress(&pX1, g_X1);
    cudaGetSymbolAddress(&pX2, g_X2);
    cudaGetSymbolAddress(&phij, g_hij);
    cudaGetSymbolAddress(&pdiP, g_diP);
    cudaGetSymbolAddress(&pE, g_E);
    cudaGetSymbolAddress(&pS, g_S);
    cudaGetSymbolAddress(&psc1, g_sc1);
    cudaGetSymbolAddress(&psh1, g_sh1);
    cudaGetSymbolAddress(&psc2, g_sc2);
    cudaGetSymbolAddress(&psh2, g_sh2);
    cudaGetSymbolAddress(&pci, g_ci);
    cudaGetSymbolAddress(&pdj, g_dj);
    cudaGetSymbolAddress(&ppos, g_pos);
    cudaGetSymbolAddress(&pperm, g_perm);
    cudaGetSymbolAddress(&plsort, g_lsort);
    cudaGetSymbolAddress(&pcls, g_cls);
    cudaGetSymbolAddress(&ptlist, g_tlist);
    cudaGetSymbolAddress(&ptcnt, g_tcnt);
    cudaGetSymbolAddress(&pAbf, g_Abf);
    cudaGetSymbolAddress(&pBbf, g_Bbf);

    float* P = (float*)pP;
    float* Q = (float*)pQ;
    float* X1 = (float*)pX1;
    float* X2 = (float*)pX2;
    float* hij = (float*)phij;
    float* diP = (float*)pdiP;
    float* E = (float*)pE;
    float* S = (float*)pS;
    float* sc1 = (float*)psc1;
    float* sh1 = (float*)psh1;
    float* sc2 = (float*)psc2;
    float* sh2 = (float*)psh2;
    float* ci = (float*)pci;
    float* dj = (float*)pdj;
    int* pos = (int*)ppos;
    int* perm = (int*)pperm;
    int* lsort = (int*)plsort;
    int* cls = (int*)pcls;
    int* tlist = (int*)ptlist;
    int* tcnt = (int*)ptcnt;
    __nv_bfloat16* Abf = (__nv_bfloat16*)pAbf;
    __nv_bfloat16* Bbf = (__nv_bfloat16*)pBbf;

    cudaFuncSetAttribute(wmma_bf16<false>,
                         cudaFuncAttributeMaxDynamicSharedMemorySize, 56320);
    cudaFuncSetAttribute(wmma_bf16<true>,
                         cudaFuncAttributeMaxDynamicSharedMemorySize, 56320);

    // 0) label ranking / permutation / tile worklist
    rank_kernel<<<8, 128>>>(labels, pos, perm, lsort, cls, tcnt);
    zero_E<<<1024, 256>>>(E);
    build_worklist<<<1, 1024>>>(lsort, tlist, tcnt);

    // 1) GEMM1 via HMMA: split conversions + wmma (split-K8 -> P planes 0..7)
    conv_feats<<<2048, 256>>>(features, Abf);
    conv_W1<<<dim3(32, 4), 256>>>(W1, Bbf);
    wmma_bf16<false><<<dim3(4, 8, 8), 256, 56320>>>(Abf, Bbf, P, 6144, 12);

    // 2) X1 = sum(P)+b1; BN1 stats
    stats_phase1<8><<<256, 256>>>(P, b1, X1, S);
    stats_phase2<<<8, 256>>>(S, g1, bt1, sc1, sh1);

    // 3) GEMM2 via HMMA: act split + W2 split + wmma split-K4 -> Q planes 0..3
    conv_act<<<256, 256>>>(X1, sc1, sh1, Abf);
    conv_wT<<<dim3(4, 4, 1), 256>>>(W2, Bbf);
    wmma_bf16<false><<<dim3(4, 8, 4), 256, 56320>>>(Abf, Bbf, Q, 768, 3);

    // 4) X2 = sum(Q)+b2; BN2 stats
    stats_phase1<4><<<256, 256>>>(Q, b2, X2, S);
    stats_phase2<<<8, 256>>>(S, g2, bt2, sc2, sh2);
    // 5) diP[pos[r]] = relu(BN2(X2[r]))
    apply_relu_perm<<<256, 256>>>(X2, sc2, sh2, pos, diP);

    // 6) GEMM3 via HMMA: di split + We1 halves split + wmma dual split-K2
    conv_act<<<256, 256>>>(X2, sc2, sh2, Abf);
    conv_wT<<<dim3(4, 4, 2), 256>>>(We1, Bbf);
    wmma_bf16<true><<<dim3(4, 8, 4), 256, 56320>>>(Abf, Bbf, Q, 768, 6);

    // 7) combine -> hi/hjb permuted (+bwe1), ci/dj permuted
    combine_cidj<<<NN, 256>>>(Q, bwe1, We2, pos, hij, hij + (size_t)NN * H, ci, dj);
    // 8) sparse edge weights (active tiles only)
    edge_sparse<<<296, 128>>>(hij, hij + (size_t)NN * H, We2, bwe2, lsort,
                              ci, dj, tlist, tcnt, E);
    // 9) GEMM4: E @ diP over per-tile class k-range
    gemm4_range<<<dim3(4, 32), 128>>>(E, diP, lsort, cls, P);
    // 10) out[perm[p]] = diP[p] + R[p]/wsum[p]
    reduce_final<<<256, 256>>>(P, E, diP, perm, out);
}

// round 14
// speedup vs baseline: 1.0685x; 1.0685x over previous
#include <cuda_runtime.h>
#include <cuda_bf16.h>
#include <mma.h>
#include <math.h>

#define NN 1024
#define H 256

typedef unsigned long long u64;
typedef unsigned int u32;

using namespace nvcuda;

// ---------------- f32x2 packed helpers (sm_103a) ----------------------------
__device__ __forceinline__ u64 add2(u64 a, u64 b) {
    u64 r; asm("add.rn.f32x2 %0,%1,%2;" : "=l"(r) : "l"(a), "l"(b)); return r;
}
__device__ __forceinline__ void fma2(u64& d, u64 a, u64 b) {
    asm("fma.rn.f32x2 %0,%1,%2,%0;" : "+l"(d) : "l"(a), "l"(b));
}
__device__ __forceinline__ float2 unpack2(u64 v) {
    float2 r; asm("mov.b64 {%0,%1},%2;" : "=f"(r.x), "=f"(r.y) : "l"(v)); return r;
}

// ---------------- cp.async helpers ------------------------------------------
__device__ __forceinline__ void cp8(void* dst_smem, const void* src) {
    unsigned d = (unsigned)__cvta_generic_to_shared(dst_smem);
    asm volatile("cp.async.ca.shared.global [%0], [%1], 8;" :: "r"(d), "l"(src));
}
__device__ __forceinline__ void cp16s(unsigned dst_smem, const void* src) {
    asm volatile("cp.async.cg.shared.global [%0], [%1], 16;" :: "r"(dst_smem), "l"(src));
}
__device__ __forceinline__ void cp_commit() {
    asm volatile("cp.async.commit_group;" ::: "memory");
}
template <int N>
__device__ __forceinline__ void cp_wait() {
    asm volatile("cp.async.wait_group %0;" :: "n"(N) : "memory");
}
__device__ __forceinline__ u32 s2u(const void* p) {
    u32 a; asm("{ .reg .u64 t; cvta.to.shared.u64 t, %1; cvt.u32.u64 %0, t; }"
               : "=r"(a) : "l"(p));
    return a;
}

__device__ __forceinline__ unsigned short bfbits(float x) {
    __nv_bfloat16 h = __float2bfloat16(x);
    return *reinterpret_cast<unsigned short*>(&h);
}
__device__ __forceinline__ float bffloat(unsigned short u) {
    __nv_bfloat16 h;
    *reinterpret_cast<unsigned short*>(&h) = u;
    return __bfloat162float(h);
}

// ---------------- scratch ----------------------------------------------------
__device__ float g_P[8 * NN * H];
__device__ float g_Q[4 * NN * H];
__device__ float g_X1[NN * H];
__device__ float g_X2[NN * H];
__device__ float g_hij[2 * NN * H];
__device__ float g_diP[NN * H];
__device__ float g_E[NN * NN];
__device__ float g_S[256 * 512];
__device__ float g_sc1[H], g_sh1[H];
__device__ float g_sc2[H], g_sh2[H];
__device__ float g_ci[NN], g_dj[NN];
__device__ int g_pos[NN], g_perm[NN], g_lsort[NN], g_cls[17];
__device__ int g_tlist[1024];
__device__ int g_tcnt[1];
__device__ __align__(16) __nv_bfloat16 g_Abf[NN * 6144];
__device__ __align__(16) __nv_bfloat16 g_Bbf[256 * 6144];
__device__ __align__(16) __nv_bfloat16 g_Wbf[3 * 256 * 768];

// ---------------- conv: features -> split-bf16 A' (K'=6144) -----------------
__global__ void conv_feats(const float* __restrict__ F, __nv_bfloat16* __restrict__ Ap) {
    const int gid = blockIdx.x * 256 + threadIdx.x;
    const int row = gid >> 9;
    const int kq = (gid & 511) * 4;
    float4 v = *(const float4*)&F[(size_t)row * 2048 + kq];
    float a[4] = {v.x, v.y, v.z, v.w};
    unsigned short hb[4], lb[4];
#pragma unroll
    for (int j = 0; j < 4; j++) {
        hb[j] = bfbits(a[j]);
        lb[j] = bfbits(a[j] - bffloat(hb[j]));
    }
    uint4 u;
    u.x = hb[0] | ((u32)lb[0] << 16);
    u.y = hb[1] | ((u32)lb[1] << 16);
    u.z = hb[2] | ((u32)lb[2] << 16);
    u.w = hb[3] | ((u32)lb[3] << 16);
    *(uint4*)&Ap[(size_t)row * 6144 + 2 * kq] = u;
    uint2 w;
    w.x = hb[0] | ((u32)hb[1] << 16);
    w.y = hb[2] | ((u32)hb[3] << 16);
    *(uint2*)&Ap[(size_t)row * 6144 + 4096 + kq] = w;
}

// ---------------- conv_weights: W1 (->Bbf) + W2/We1 halves (->Wbf) ----------
// blocks 0..127: W1 (kb=id&31, nb=id>>5); 128..143: W2; 144..175: We1 z halves
__global__ void conv_weights(const float* __restrict__ W1, const float* __restrict__ W2,
                             const float* __restrict__ We1,
                             __nv_bfloat16* __restrict__ Bbf,
                             __nv_bfloat16* __restrict__ Wbf) {
    __shared__ float sW[64][65];
    const int id = blockIdx.x;
    const int t = threadIdx.x;

    const float* Ws;
    __nv_bfloat16* Bd;
    int kb, nb, ldK;
    if (id < 128) {
        kb = id & 31; nb = id >> 5;
        Ws = W1; Bd = Bbf; ldK = 6144;
    } else if (id < 144) {
        int q = id - 128;
        kb = q & 3; nb = q >> 2;
        Ws = W2; Bd = Wbf; ldK = 768;
    } else {
        int q = id - 144;
        int z = q >> 4; q &= 15;
        kb = q & 3; nb = q >> 2;
        Ws = We1 + (size_t)z * 256 * 256;
        Bd = Wbf + (size_t)(1 + z) * 256 * 768;
        ldK = 768;
    }
    const int sec2 = (ldK == 6144) ? 4096 : 512;
    const int ldh = ldK >> 1;   // u32 stride of a FULL row (fixed from R13)

#pragma unroll
    for (int e = 0; e < 16; e++) {
        int iid = t + e * 256;
        int kr = iid >> 6, nc = iid & 63;
        sW[kr][nc] = Ws[(size_t)(kb * 64 + kr) * 256 + nb * 64 + nc];
    }
    __syncthreads();
#pragma unroll
    for (int e = 0; e < 16; e++) {
        int iid = t + e * 256;
        int nr = iid >> 6, kc = iid & 63;
        float x = sW[kc][nr];
        unsigned short hb = bfbits(x);
        unsigned short lb = bfbits(x - bffloat(hb));
        int ng = nb * 64 + nr, kg = kb * 64 + kc;
        ((u32*)Bd)[(size_t)ng * ldh + kg] = hb | ((u32)hb << 16);
        *reinterpret_cast<unsigned short*>(&Bd[(size_t)ng * ldK + sec2 + kg]) = lb;
    }
}

// ---------------- conv_act: relu(BN(X)) -> split bf16 [1024][768] (+diP) ----
template <bool DIP>
__global__ void conv_act(const float* __restrict__ X, const float* __restrict__ sc,
                         const float* __restrict__ sh, __nv_bfloat16* __restrict__ Ap,
                         const int* __restrict__ pos, float* __restrict__ diP) {
    const int gid = blockIdx.x * 256 + threadIdx.x;
    const int row = gid >> 6;
    const int c4 = gid & 63;
    const int kq = c4 * 4;
    float4 v = ((const float4*)X)[(size_t)row * 64 + c4];
    float4 s = ((const float4*)sc)[c4];
    float4 h = ((const float4*)sh)[c4];
    float a[4];
    a[0] = fmaxf(fmaf(v.x, s.x, h.x), 0.f);
    a[1] = fmaxf(fmaf(v.y, s.y, h.y), 0.f);
    a[2] = fmaxf(fmaf(v.z, s.z, h.z), 0.f);
    a[3] = fmaxf(fmaf(v.w, s.w, h.w), 0.f);
    if (DIP) {
        float4 d = make_float4(a[0], a[1], a[2], a[3]);
        ((float4*)diP)[(size_t)pos[row] * 64 + c4] = d;
    }
    unsigned short hb[4], lb[4];
#pragma unroll
    for (int j = 0; j < 4; j++) {
        hb[j] = bfbits(a[j]);
        lb[j] = bfbits(a[j] - bffloat(hb[j]));
    }
    uint4 u;
    u.x = hb[0] | ((u32)lb[0] << 16);
    u.y = hb[1] | ((u32)lb[1] << 16);
    u.z = hb[2] | ((u32)lb[2] << 16);
    u.w = hb[3] | ((u32)lb[3] << 16);
    *(uint4*)&Ap[(size_t)row * 768 + 2 * kq] = u;
    uint2 w;
    w.x = hb[0] | ((u32)hb[1] << 16);
    w.y = hb[2] | ((u32)hb[3] << 16);
    *(uint2*)&Ap[(size_t)row * 768 + 512 + kq] = w;
}

// ---------------- generic wmma GEMM: C[1024,256] = A @ B^T -------------------
template <bool DUAL>
__global__ __launch_bounds__(256) void wmma_bf16(
    const __nv_bfloat16* __restrict__ A, const __nv_bfloat16* __restrict__ B,
    float* __restrict__ C0, int ld, int kchunksPerZ) {
    extern __shared__ char dsm[];
    char* base = (char*)(((size_t)dsm + 1023) & ~(size_t)1023);
    __nv_bfloat16* smA[2] = {(__nv_bfloat16*)base,
                             (__nv_bfloat16*)(base + 18432)};
    __nv_bfloat16* smB[2] = {(__nv_bfloat16*)(base + 36864),
                             (__nv_bfloat16*)(base + 46080)};
    const u32 uA[2] = {s2u(smA[0]), s2u(smA[1])};
    const u32 uB[2] = {s2u(smB[0]), s2u(smB[1])};

    const int t = threadIdx.x;
    const int wid = t >> 5;
    const int wm = wid >> 1;
    const int wn = wid & 1;
    const int J = blockIdx.x * 64;
    const int I = blockIdx.y * 128;
    const int z = blockIdx.z;
    const int kbase = (DUAL ? (z & 1) : z) * kchunksPerZ * 64;
    const __nv_bfloat16* Bp = DUAL ? (B + (size_t)(z >> 1) * 256 * ld) : B;

    auto stage = [&](int chunk, int buf) {
        const int k0 = kbase + chunk * 64;
#pragma unroll
        for (int e = 0; e < 4; e++) {
            int id = t + e * 256;
            int r = id >> 3, c = id & 7;
            cp16s(uA[buf] + r * 144 + c * 16,
                  A + (size_t)(I + r) * ld + k0 + c * 8);
        }
#pragma unroll
        for (int e = 0; e < 2; e++) {
            int id = t + e * 256;
            int r = id >> 3, c = id & 7;
            cp16s(uB[buf] + r * 144 + c * 16,
                  Bp + (size_t)(J + r) * ld + k0 + c * 8);
        }
    };

    wmma::fragment<wmma::accumulator, 16, 16, 16, float> acc[2][2];
#pragma unroll
    for (int i = 0; i < 2; i++)
#pragma unroll
        for (int j = 0; j < 2; j++) wmma::fill_fragment(acc[i][j], 0.0f);

    stage(0, 0);
    cp_commit();

    for (int c = 0; c < kchunksPerZ; c++) {
        const int buf = c & 1;
        if (c + 1 < kchunksPerZ) {
            stage(c + 1, buf ^ 1);
            cp_commit();
            cp_wait<1>();
        } else {
            cp_wait<0>();
        }
        __syncthreads();
#pragma unroll
        for (int k16 = 0; k16 < 4; k16++) {
            wmma::fragment<wmma::matrix_a, 16, 16, 16, __nv_bfloat16,
                           wmma::row_major> af[2];
            wmma::fragment<wmma::matrix_b, 16, 16, 16, __nv_bfloat16,
                           wmma::col_major> bf[2];
#pragma unroll
            for (int i = 0; i < 2; i++)
                wmma::load_matrix_sync(
                    af[i], smA[buf] + (wm * 32 + i * 16) * 72 + k16 * 16, 72);
#pragma unroll
            for (int j = 0; j < 2; j++)
                wmma::load_matrix_sync(
                    bf[j], smB[buf] + (wn * 32 + j * 16) * 72 + k16 * 16, 72);
#pragma unroll
            for (int i = 0; i < 2; i++)
#pragma unroll
                for (int j = 0; j < 2; j++)
                    wmma::mma_sync(acc[i][j], af[i], bf[j], acc[i][j]);
        }
        __syncthreads();
    }

    float* Cp = C0 + (size_t)z * NN * H;
#pragma unroll
    for (int i = 0; i < 2; i++)
#pragma unroll
        for (int j = 0; j < 2; j++)
            wmma::store_matrix_sync(
                Cp + (size_t)(I + wm * 32 + i * 16) * H + J + wn * 32 + j * 16,
                acc[i][j], H, wmma::mem_row_major);
}

// ---------------- GEMM4: E(perm, block-diag) @ diP, dynamic k-range ---------
__global__ __launch_bounds__(128) void gemm4_range(
    const float* __restrict__ E, const float* __restrict__ diP,
    const int* __restrict__ lsort, const int* __restrict__ cls,
    float* __restrict__ C) {
    __shared__ float As[2][32][20];
    __shared__ float Bs[2][64][20];

    const int t = threadIdx.x;
    const int tx = t & 15;
    const int ty = t >> 4;
    const int I = blockIdx.y * 32;
    const int J = blockIdx.x * 64;

    const int lmin = lsort[I];
    const int lmax = lsort[I + 31];
    const int kmin = cls[lmin] & ~15;
    int kmax = (cls[lmax + 1] + 15) & ~15;
    if (kmax > NN) kmax = NN;
    const int kiters = (kmax - kmin) >> 4;

    float4 fa;
    float fb[8];
    const int ar = t >> 2, ac4 = t & 3;
    const int bc = t & 63, bkh = (t >> 6) * 8;

    auto loadA = [&](int kt) {
        const int kc = kmin + kt * 16 + ac4 * 4;
        fa = *(const float4*)&E[(size_t)(I + ar) * NN + kc];
    };
    auto loadB = [&](int kt) {
        const int k0 = kmin + kt * 16 + bkh;
#pragma unroll
        for (int e = 0; e < 8; e++)
            fb[e] = diP[(size_t)(k0 + e) * H + J + bc];
    };
    auto stageS = [&](int buf) {
        *(float4*)&As[buf][ar][ac4 * 4] = fa;
        *(float4*)&Bs[buf][bc][bkh] = make_float4(fb[0], fb[1], fb[2], fb[3]);
        *(float4*)&Bs[buf][bc][bkh + 4] = make_float4(fb[4], fb[5], fb[6], fb[7]);
    };

    u64 acc[4][4];
#pragma unroll
    for (int m = 0; m < 4; m++)
#pragma unroll
        for (int n = 0; n < 4; n++) acc[m][n] = 0ull;

    loadA(0); loadB(0);
    stageS(0);
    __syncthreads();

    for (int kt = 0; kt < kiters; kt++) {
        const int buf = kt & 1;
        if (kt + 1 < kiters) { loadA(kt + 1); loadB(kt + 1); }
#pragma unroll
        for (int g = 0; g < 4; g++) {
            float4 av[4], bv[4];
#pragma unroll
            for (int m = 0; m < 4; m++)
                av[m] = *(const float4*)&As[buf][ty * 4 + m][g * 4];
#pragma unroll
            for (int n = 0; n < 4; n++)
                bv[n] = *(const float4*)&Bs[buf][tx + n * 16][g * 4];
#pragma unroll
            for (int m = 0; m < 4; m++) {
                const u64 a01 = *(const u64*)&av[m].x;
                const u64 a23 = *(const u64*)&av[m].z;
#pragma unroll
                for (int n = 0; n < 4; n++) {
                    fma2(acc[m][n], a01, *(const u64*)&bv[n].x);
                    fma2(acc[m][n], a23, *(const u64*)&bv[n].z);
                }
            }
        }
        if (kt + 1 < kiters) {
            stageS(buf ^ 1);
            __syncthreads();
        }
    }

#pragma unroll
    for (int m = 0; m < 4; m++) {
        const int row = I + ty * 4 + m;
#pragma unroll
        for (int n = 0; n < 4; n++) {
            const int col = J + tx + n * 16;
            float2 p = unpack2(acc[m][n]);
            C[(size_t)row * H + col] = p.x + p.y;
        }
    }
}

// ---------------- BN stats phase1 / phase2 -----------------------------------
template <int NP>
__global__ void stats_phase1(const float* __restrict__ P, const float* __restrict__ bias,
                             float* __restrict__ X, float* __restrict__ S) {
    const int t = threadIdx.x;
    const int c4 = t & 63;
    const int rg = t >> 6;
    const int row = blockIdx.x * 4 + rg;
    float4 bv = ((const float4*)bias)[c4];
    constexpr size_t Q = NN * H / 4;
    size_t idx = (size_t)row * 64 + c4;
    float4 v = bv;
#pragma unroll
    for (int p = 0; p < NP; p++) {
        float4 a = ((const float4*)P)[(size_t)p * Q + idx];
        v.x += a.x; v.y += a.y; v.z += a.z; v.w += a.w;
    }
    ((float4*)X)[idx] = v;
    float4 q;
    q.x = v.x * v.x; q.y = v.y * v.y; q.z = v.z * v.z; q.w = v.w * v.w;
    __shared__ float4 sm[4][64], qm[4][64];
    sm[rg][c4] = v;
    qm[rg][c4] = q;
    __syncthreads();
    if (t < 64) {
        float4 S4 = make_float4(0.f, 0.f, 0.f, 0.f);
        float4 Q4 = make_float4(0.f, 0.f, 0.f, 0.f);
#pragma unroll
        for (int p = 0; p < 4; p++) {
            float4 a = sm[p][t], b = qm[p][t];
            S4.x += a.x; S4.y += a.y; S4.z += a.z; S4.w += a.w;
            Q4.x += b.x; Q4.y += b.y; Q4.z += b.z; Q4.w += b.w;
        }
        ((float4*)S)[blockIdx.x * 128 + t] = S4;
        ((float4*)S)[blockIdx.x * 128 + 64 + t] = Q4;
    }
}

__global__ void stats_phase2(const float* __restrict__ S, const float* __restrict__ g,
                             const float* __restrict__ bt, float* __restrict__ sc,
                             float* __restrict__ sh) {
    const int t = threadIdx.x;
    const int c = blockIdx.x * 32 + (t & 31);
    const int pg = t >> 5;
    float s = 0.f, q = 0.f;
#pragma unroll
    for (int p = pg; p < 256; p += 8) {
        s += S[p * 512 + c];
        q += S[p * 512 + 256 + c];
    }
    __shared__ float sm[8][32], qm[8][32];
    sm[pg][t & 31] = s;
    qm[pg][t & 31] = q;
    __syncthreads();
    if (t < 32) {
        float S_ = 0.f, Q_ = 0.f;
#pragma unroll
        for (int p = 0; p < 8; p++) { S_ += sm[p][t]; Q_ += qm[p][t]; }
        const int col = blockIdx.x * 32 + t;
        float m = S_ * (1.f / NN);
        float var = Q_ * (1.f / NN) - m * m;
        float scv = g[col] * rsqrtf(var + 1e-5f);
        sc[col] = scv;
        sh[col] = bt[col] - m * scv;
    }
}

// ---------------- rank/sort kernel -------------------------------------------
__global__ void rank_kernel(const int* __restrict__ labels, int* __restrict__ pos,
                            int* __restrict__ perm, int* __restrict__ lsort,
                            int* __restrict__ cls, int* __restrict__ tcnt) {
    __shared__ int sl[NN];
    const int t = threadIdx.x;
    const int node = blockIdx.x * 128 + t;
#pragma unroll
    for (int e = 0; e < NN / 128; e++) sl[t + e * 128] = labels[t + e * 128];
    __syncthreads();
    const int my = sl[node];
    int r = 0;
#pragma unroll 8
    for (int j = 0; j < NN; j++) {
        int l = sl[j];
        r += (l < my) || (l == my && j < node);
    }
    pos[node] = r;
    perm[r] = node;
    lsort[r] = my;
    if (blockIdx.x == 0) {
        if (t <= 16) {
            int c = 0;
#pragma unroll 8
            for (int j = 0; j < NN; j++) c += (sl[j] < t);
            cls[t] = c;
        }
        if (t == 17) tcnt[0] = 0;
    }
}

// ---------------- combine GEMM3 partials + ci/dj (permuted writes) -----------
__global__ void combine_cidj(const float* __restrict__ Q, const float* __restrict__ bwe1,
                             const float* __restrict__ We2, const int* __restrict__ pos,
                             float* __restrict__ hi, float* __restrict__ hjb,
                             float* __restrict__ ci, float* __restrict__ dj) {
    const int r = blockIdx.x;
    const int pr = pos[r];
    const int t = threadIdx.x;
    const bool isB = t >= 128;
    const int tt = t & 127;
    constexpr size_t PL = (size_t)NN * H;
    const float* P0 = Q + (isB ? 2 * PL : 0);
    const float* P1 = P0 + PL;
    float* dst = isB ? hjb : hi;
    float partial = 0.f;
#pragma unroll
    for (int e = 0; e < 2; e++) {
        const int c = tt + e * 128;
        float v = P0[(size_t)r * H + c] + P1[(size_t)r * H + c];
        if (isB) v += bwe1[c];
        dst[(size_t)pr * H + c] = v;
        partial = fmaf(v, We2[c], partial);
    }
#pragma unroll
    for (int o = 16; o > 0; o >>= 1) partial += __shfl_xor_sync(~0u, partial, o);
    __shared__ float red[8];
    if ((t & 31) == 0) red[t >> 5] = partial;
    __syncthreads();
    if (t == 0) ci[pr] = 0.5f * (red[0] + red[1] + red[2] + red[3]);
    if (t == 128) dj[pr] = 0.5f * (red[4] + red[5] + red[6] + red[7]);
}

// ---------------- worklist of active 32x32 tiles -----------------------------
__global__ void build_worklist(const int* __restrict__ lsort, int* __restrict__ tlist,
                               int* __restrict__ tcnt) {
    const int t = threadIdx.x;
    const int ti = t >> 5, tj = t & 31;
    const int I = ti * 32, J = tj * 32;
    bool act = (lsort[I] <= lsort[J + 31]) && (lsort[J] <= lsort[I + 31]);
    if (act) {
        int k = atomicAdd(tcnt, 1);
        tlist[k] = (ti << 16) | tj;
    }
}

// ---------------- sparse edge kernel -----------------------------------------
__global__ __launch_bounds__(128) void edge_sparse(
    const float* __restrict__ hi, const float* __restrict__ hjb,
    const float* __restrict__ We2, const float* __restrict__ bwe2,
    const int* __restrict__ lsort,
    const float* __restrict__ ci, const float* __restrict__ dj,
    const int* __restrict__ tlist, const int* __restrict__ tcnt,
    float* __restrict__ E) {
    __shared__ float2 sa[2][32][16];
    __shared__ float2 sb[2][32][16];
    __shared__ float sw[256];

    const int t = threadIdx.x;
    const int tx = t & 15;
    const int ty = t >> 4;
    sw[t] = 0.5f * We2[t];
    sw[t + 128] = 0.5f * We2[t + 128];
    const int n = tcnt[0];
    const float bw = bwe2[0];

    for (int w = blockIdx.x; w < n; w += gridDim.x) {
        const int tile = tlist[w];
        const int I = (tile >> 16) * 32;
        const int J = (tile & 0xffff) * 32;

        auto stage = [&](int c) {
            const int buf = c & 1;
            const int hoff = c * 32;
#pragma unroll
            for (int k = 0; k < 8; k++) {
                int p = t + k * 128;
                if (p < 512) {
                    int r = p >> 4, c2 = p & 15;
                    cp8(&sa[buf][r][c2 ^ (r & 15)],
                        hi + (size_t)(I + r) * H + hoff + c2 * 2);
                } else {
                    int q = p - 512;
                    int r = q >> 4, c2 = q & 15;
                    cp8(&sb[buf][r][c2 ^ (r & 15)],
                        hjb + (size_t)(J + r) * H + hoff + c2 * 2);
                }
            }
        };

        u64 acc[4][2];
#pragma unroll
        for (int m = 0; m < 4; m++)
#pragma unroll
            for (int nn2 = 0; nn2 < 2; nn2++) acc[m][nn2] = 0ull;

        stage(0);
        cp_commit();

        for (int c = 0; c < 8; c++) {
            if (c < 7) {
                stage(c + 1);
                cp_commit();
                cp_wait<1>();
            } else {
                cp_wait<0>();
            }
            __syncthreads();
            const int buf = c & 1;
            const float* swc = &sw[c * 32];
#pragma unroll
            for (int hp = 0; hp < 16; hp++) {
                u64 wv = *(const u64*)&swc[hp * 2];
                u64 aP[4], bP[2];
#pragma unroll
                for (int m = 0; m < 4; m++) {
                    const int r = ty + m * 8;
                    aP[m] = *(const u64*)&sa[buf][r][hp ^ (r & 15)];
                }
#pragma unroll
                for (int nn2 = 0; nn2 < 2; nn2++) {
                    const int r = tx + nn2 * 16;
                    bP[nn2] = *(const u64*)&sb[buf][r][hp ^ (r & 15)];
                }
#pragma unroll
                for (int m = 0; m < 4; m++)
#pragma unroll
                    for (int nn2 = 0; nn2 < 2; nn2++) {
                        u64 s = add2(aP[m], bP[nn2]) & 0x7FFFFFFF7FFFFFFFull;
                        fma2(acc[m][nn2], s, wv);
                    }
            }
            __syncthreads();
        }

#pragma unroll
        for (int m = 0; m < 4; m++) {
            const int i = I + ty + m * 8;
            const int la = lsort[i];
            const float cv = ci[i] + bw;
#pragma unroll
            for (int nn2 = 0; nn2 < 2; nn2++) {
                const int j = J + tx + nn2 * 16;
                float2 p = unpack2(acc[m][nn2]);
                float logit = p.x + p.y + cv + dj[j];
                float e = (la == lsort[j] && i != j)
                              ? 1.f / (1.f + __expf(-logit)) : 0.f;
                E[(size_t)i * NN + j] = e;
            }
        }
    }
}

// ---------------- final: wsum over class range; out[perm[p]] ----------------
__global__ void reduce_final(const float* __restrict__ P, const float* __restrict__ E,
                             const float* __restrict__ diP, const int* __restrict__ perm,
                             const int* __restrict__ lsort, const int* __restrict__ cls,
                             float* __restrict__ out) {
    const int t = threadIdx.x;
    const int rg = t >> 6;
    const int c4 = t & 63;
    const int p = blockIdx.x * 4 + rg;

    const int l = lsort[p];
    const int j0 = cls[l], j1 = cls[l + 1];
    float s = 0.f;
    const float* Er = E + (size_t)p * NN;
    for (int j = j0 + c4; j < j1; j += 64) s += Er[j];
#pragma unroll
    for (int o = 16; o > 0; o >>= 1) s += __shfl_xor_sync(~0u, s, o);
    __shared__ float sm[8];
    if ((t & 31) == 0) sm[t >> 5] = s;
    __syncthreads();
    const float w = sm[rg * 2] + sm[rg * 2 + 1];
    const float inv = w > 0.f ? 1.f / w : 0.f;

    const size_t idx = (size_t)p * 64 + c4;
    float4 a = ((const float4*)P)[idx];
    float4 d = ((const float4*)diP)[idx];
    float4 o;
    o.x = fmaf(a.x, inv, d.x);
    o.y = fmaf(a.y, inv, d.y);
    o.z = fmaf(a.z, inv, d.z);
    o.w = fmaf(a.w, inv, d.w);
    ((float4*)out)[(size_t)perm[p] * 64 + c4] = o;
}

// ---------------- launch -----------------------------------------------------
extern "C" void kernel_launch(void* const* d_in, const int* in_sizes, int n_in,
                              void* d_out, int out_size) {
    const float* features = (const float*)d_in[0];
    const int* labels = (const int*)d_in[1];
    const float* W1 = (const float*)d_in[2];
    const float* b1 = (const float*)d_in[3];
    const float* g1 = (const float*)d_in[4];
    const float* bt1 = (const float*)d_in[5];
    const float* W2 = (const float*)d_in[6];
    const float* b2 = (const float*)d_in[7];
    const float* g2 = (const float*)d_in[8];
    const float* bt2 = (const float*)d_in[9];
    const float* We1 = (const float*)d_in[10];
    const float* bwe1 = (const float*)d_in[11];
    const float* We2 = (const float*)d_in[12];
    const float* bwe2 = (const float*)d_in[13];
    float* out = (float*)d_out;

    void *pP, *pQ, *pX1, *pX2, *phij, *pdiP, *pE, *pS;
    void *psc1, *psh1, *psc2, *psh2, *pci, *pdj;
    void *ppos, *pperm, *plsort, *pcls, *ptlist, *ptcnt, *pAbf, *pBbf, *pWbf;
    cudaGetSymbolAddress(&pP, g_P);
    cudaGetSymbolAddress(&pQ, g_Q);
    cudaGetSymbolAddress(&pX1, g_X1);
    cudaGetSymbolAddress(&pX2, g_X2);
    cudaGetSymbolAddress(&phij, g_hij);
    cudaGetSymbolAddress(&pdiP, g_diP);
    cudaGetSymbolAddress(&pE, g_E);
    cudaGetSymbolAddress(&pS, g_S);
    cudaGetSymbolAddress(&psc1, g_sc1);
    cudaGetSymbolAddress(&psh1, g_sh1);
    cudaGetSymbolAddress(&psc2, g_sc2);
    cudaGetSymbolAddress(&psh2, g_sh2);
    cudaGetSymbolAddress(&pci, g_ci);
    cudaGetSymbolAddress(&pdj, g_dj);
    cudaGetSymbolAddress(&ppos, g_pos);
    cudaGetSymbolAddress(&pperm, g_perm);
    cudaGetSymbolAddress(&plsort, g_lsort);
    cudaGetSymbolAddress(&pcls, g_cls);
    cudaGetSymbolAddress(&ptlist, g_tlist);
    cudaGetSymbolAddress(&ptcnt, g_tcnt);
    cudaGetSymbolAddress(&pAbf, g_Abf);
    cudaGetSymbolAddress(&pBbf, g_Bbf);
    cudaGetSymbolAddress(&pWbf, g_Wbf);

    float* P = (float*)pP;
    float* Q = (float*)pQ;
    float* X1 = (float*)pX1;
    float* X2 = (float*)pX2;
    float* hij = (float*)phij;
    float* diP = (float*)pdiP;
    float* E = (float*)pE;
    float* S = (float*)pS;
    float* sc1 = (float*)psc1;
    float* sh1 = (float*)psh1;
    float* sc2 = (float*)psc2;
    float* sh2 = (float*)psh2;
    float* ci = (float*)pci;
    float* dj = (float*)pdj;
    int* pos = (int*)ppos;
    int* perm = (int*)pperm;
    int* lsort = (int*)plsort;
    int* cls = (int*)pcls;
    int* tlist = (int*)ptlist;
    int* tcnt = (int*)ptcnt;
    __nv_bfloat16* Abf = (__nv_bfloat16*)pAbf;
    __nv_bfloat16* Bbf = (__nv_bfloat16*)pBbf;
    __nv_bfloat16* Wbf = (__nv_bfloat16*)pWbf;

    cudaFuncSetAttribute(wmma_bf16<false>,
                         cudaFuncAttributeMaxDynamicSharedMemorySize, 56320);
    cudaFuncSetAttribute(wmma_bf16<true>,
                         cudaFuncAttributeMaxDynamicSharedMemorySize, 56320);

    // 0) label ranking / worklist / all weight conversions
    rank_kernel<<<8, 128>>>(labels, pos, perm, lsort, cls, tcnt);
    build_worklist<<<1, 1024>>>(lsort, tlist, tcnt);
    conv_weights<<<176, 256>>>(W1, W2, We1, Bbf, Wbf);

    // 1) GEMM1 via HMMA: A split + wmma split-K8 -> P planes 0..7
    conv_feats<<<2048, 256>>>(features, Abf);
    wmma_bf16<false><<<dim3(4, 8, 8), 256, 56320>>>(Abf, Bbf, P, 6144, 12);

    // 2) X1 = sum(P)+b1; BN1 stats
    stats_phase1<8><<<256, 256>>>(P, b1, X1, S);
    stats_phase2<<<8, 256>>>(S, g1, bt1, sc1, sh1);

    // 3) GEMM2 via HMMA: act split + wmma split-K4 -> Q planes 0..3
    conv_act<false><<<256, 256>>>(X1, sc1, sh1, Abf, nullptr, nullptr);
    wmma_bf16<false><<<dim3(4, 8, 4), 256, 56320>>>(Abf, Wbf, Q, 768, 3);

    // 4) X2 = sum(Q)+b2; BN2 stats
    stats_phase1<4><<<256, 256>>>(Q, b2, X2, S);
    stats_phase2<<<8, 256>>>(S, g2, bt2, sc2, sh2);

    // 5+6) act split of X2 (also writes diP permuted) + GEMM3 wmma dual
    conv_act<true><<<256, 256>>>(X2, sc2, sh2, Abf, pos, diP);
    wmma_bf16<true><<<dim3(4, 8, 4), 256, 56320>>>(Abf, Wbf + (size_t)256 * 768, Q, 768, 6);

    // 7) combine -> hi/hjb permuted (+bwe1), ci/dj permuted
    combine_cidj<<<NN, 256>>>(Q, bwe1, We2, pos, hij, hij + (size_t)NN * H, ci, dj);
    // 8) sparse edge weights (active tiles only)
    edge_sparse<<<296, 128>>>(hij, hij + (size_t)NN * H, We2, bwe2, lsort,
                              ci, dj, tlist, tcnt, E);
    // 9) GEMM4: E @ diP over per-tile class k-range
    gemm4_range<<<dim3(4, 32), 128>>>(E, diP, lsort, cls, P);
    // 10) out[perm[p]] = diP[p] + R[p]/wsum[p] (wsum over class range)
    reduce_final<<<256, 256>>>(P, E, diP, perm, lsort, cls, out);
}